// round 1
// baseline (speedup 1.0000x reference)
#include <cuda_runtime.h>
#include <cuda_bf16.h>
#include <cstdint>

#define N_DIM   1024
#define K_DIM   64
#define OUT_DIM 64

// ---------------- device scratch (no allocation allowed) ----------------
__device__ float g_CP[N_DIM * K_DIM];     // row means   (reference "col_pool")
__device__ float g_RP[N_DIM * K_DIM];     // column means (reference "row_pool")
__device__ float g_D [N_DIM * K_DIM];     // diagonal rows X[i,i,:]
__device__ float g_Pall [K_DIM];
__device__ float g_Pdiag[K_DIM];
__device__ float g_Frow[N_DIM * OUT_DIM];
__device__ float g_Fcol[N_DIM * OUT_DIM];
__device__ float g_G   [N_DIM * OUT_DIM];

// ---------------- packed f32x2 helpers ----------------
__device__ __forceinline__ unsigned long long pack_dup(float x) {
    unsigned long long r;
    asm("mov.b64 %0, {%1, %1};" : "=l"(r) : "f"(x));
    return r;
}
__device__ __forceinline__ unsigned long long fma2(unsigned long long a,
                                                   unsigned long long b,
                                                   unsigned long long c) {
    unsigned long long d;
    asm("fma.rn.f32x2 %0, %1, %2, %3;" : "=l"(d) : "l"(a), "l"(b), "l"(c));
    return d;
}
__device__ __forceinline__ void unpack2(unsigned long long v, float& lo, float& hi) {
    asm("mov.b64 {%0, %1}, %2;" : "=f"(lo), "=f"(hi) : "l"(v));
}

// ---------------- pooling kernels ----------------
// CP[i] = mean over c of X[i*N + c]  ; D[i] = X[i*N + i]
__global__ __launch_bounds__(256) void rowpool_kernel(const float* __restrict__ X) {
    int i   = blockIdx.x;
    int tid = threadIdx.x;
    int c4  = tid >> 6;          // 0..3
    int k   = tid & 63;
    const float* base = X + (size_t)i * N_DIM * K_DIM;
    float s = 0.f;
#pragma unroll 4
    for (int c = c4; c < N_DIM; c += 4) s += base[c * K_DIM + k];
    __shared__ float red[256];
    red[tid] = s;
    __syncthreads();
    if (c4 == 0) {
        float v = red[k] + red[64 + k] + red[128 + k] + red[192 + k];
        g_CP[i * K_DIM + k] = v * (1.0f / N_DIM);
        g_D [i * K_DIM + k] = base[i * K_DIM + k];
    }
}

// RP[j] = mean over r of X[r*N + j]
__global__ __launch_bounds__(256) void colpool_kernel(const float* __restrict__ X) {
    int j   = blockIdx.x;
    int tid = threadIdx.x;
    int r4  = tid >> 6;
    int k   = tid & 63;
    float s = 0.f;
#pragma unroll 4
    for (int r = r4; r < N_DIM; r += 4)
        s += X[((size_t)r * N_DIM + j) * K_DIM + k];
    __shared__ float red[256];
    red[tid] = s;
    __syncthreads();
    if (r4 == 0) {
        float v = red[k] + red[64 + k] + red[128 + k] + red[192 + k];
        g_RP[j * K_DIM + k] = v * (1.0f / N_DIM);
    }
}

// Pall[k] = mean_i CP[i][k] ; Pdiag[k] = mean_i D[i][k]
__global__ __launch_bounds__(256) void allpool_kernel() {
    int tid = threadIdx.x;
    int i4  = tid >> 6;
    int k   = tid & 63;
    float sa = 0.f, sd = 0.f;
#pragma unroll 4
    for (int i = i4; i < N_DIM; i += 4) {
        sa += g_CP[i * K_DIM + k];
        sd += g_D [i * K_DIM + k];
    }
    __shared__ float ra[256], rd[256];
    ra[tid] = sa; rd[tid] = sd;
    __syncthreads();
    if (i4 == 0) {
        g_Pall [k] = (ra[k] + ra[64 + k] + ra[128 + k] + ra[192 + k]) * (1.0f / N_DIM);
        g_Pdiag[k] = (rd[k] + rd[64 + k] + rd[128 + k] + rd[192 + k]) * (1.0f / N_DIM);
    }
}

// ---------------- per-row/col feature combine (tiny GEMMs) ----------------
__global__ __launch_bounds__(64) void combine_kernel(const float* __restrict__ W) {
    int i = blockIdx.x;
    int o = threadIdx.x;
    __shared__ float rp[64], cp[64], dd[64], pa[64], pd[64];
    rp[o] = g_RP[i * 64 + o];
    cp[o] = g_CP[i * 64 + o];
    dd[o] = g_D [i * 64 + o];
    pa[o] = g_Pall[o];
    pd[o] = g_Pdiag[o];
    __syncthreads();

    float fr = 0.f, fc = 0.f, gg = 0.f;
#pragma unroll 4
    for (int k = 0; k < 64; k++) {
        float rpk = rp[k], cpk = cp[k], ddk = dd[k], pak = pa[k], pdk = pd[k];
        // W layout: W[w][k][o] = W[(w*64 + k)*64 + o]
        fr += rpk * W[(4 * 64 + k) * 64 + o];
        fr += cpk * W[(5 * 64 + k) * 64 + o];
        fr += ddk * W[(14 * 64 + k) * 64 + o];
        fr += pak * W[(7 * 64 + k) * 64 + o];
        fr += pdk * W[(12 * 64 + k) * 64 + o];

        fc += rpk * W[(3 * 64 + k) * 64 + o];
        fc += cpk * W[(6 * 64 + k) * 64 + o];
        fc += ddk * W[(13 * 64 + k) * 64 + o];

        gg += ddk * W[(2 * 64 + k) * 64 + o];
        gg += rpk * W[(10 * 64 + k) * 64 + o];
        gg += cpk * W[(11 * 64 + k) * 64 + o];
        gg += pak * W[(9 * 64 + k) * 64 + o];
        gg += pdk * W[(8 * 64 + k) * 64 + o];
    }
    g_Frow[i * 64 + o] = fr;
    g_Fcol[i * 64 + o] = fc;
    g_G   [i * 64 + o] = gg;
}

// ---------------- main fused pass ----------------
// out[(r,c)] = X[(r,c)]@W0 + X[(c,r)]@W1 + Frow[r] + Fcol[c] + [r==c]*G[r]
// Tile: 16x16 entries (256), 256 threads, per-thread 8 entries x 8 outputs.
// Dynamic smem: Xs[64][256], XTs[64][256], W0s[64][64], W1s[64][64] = 160 KB.
__global__ __launch_bounds__(256, 1) void main_kernel(const float* __restrict__ X,
                                                      const float* __restrict__ W,
                                                      float* __restrict__ out) {
    extern __shared__ float sm[];
    float* Xs  = sm;                 // [k][t]   64*256
    float* XTs = sm + 64 * 256;      // [k][t]
    float* w0s = sm + 2 * 64 * 256;  // [k][o]   64*64
    float* w1s = w0s + 64 * 64;

    const int tid = threadIdx.x;
    const int r0 = blockIdx.y * 16;
    const int c0 = blockIdx.x * 16;

    // --- stage W0, W1 ---
    {
        const float4* w0g = (const float4*)W;                  // W[0]
        const float4* w1g = (const float4*)(W + 64 * 64);      // W[1]
        float4* d0 = (float4*)w0s;
        float4* d1 = (float4*)w1s;
#pragma unroll
        for (int idx = tid; idx < 1024; idx += 256) {
            d0[idx] = w0g[idx];
            d1[idx] = w1g[idx];
        }
    }

    // --- stage X tile (direct) and X^T tile ---
    {
        int t  = tid;                 // one entry per thread
        int er = t >> 4, ec = t & 15;
        size_t s  = ((size_t)(r0 + er) * N_DIM + (c0 + ec)) * K_DIM;
        size_t st = ((size_t)(c0 + ec) * N_DIM + (r0 + er)) * K_DIM;
        const float4* xs4 = (const float4*)(X + s);
        const float4* xt4 = (const float4*)(X + st);
#pragma unroll
        for (int kq = 0; kq < 16; kq++) {
            float4 v  = xs4[kq];
            float4 vt = xt4[kq];
            int kb = kq * 4;
            Xs [(kb + 0) * 256 + t] = v.x;  Xs [(kb + 1) * 256 + t] = v.y;
            Xs [(kb + 2) * 256 + t] = v.z;  Xs [(kb + 3) * 256 + t] = v.w;
            XTs[(kb + 0) * 256 + t] = vt.x; XTs[(kb + 1) * 256 + t] = vt.y;
            XTs[(kb + 2) * 256 + t] = vt.z; XTs[(kb + 3) * 256 + t] = vt.w;
        }
    }
    __syncthreads();

    // --- register-tiled compute: 8 entries x 8 outputs, packed f32x2 ---
    const int og = tid & 7;          // output group: outputs og*8 .. og*8+7
    const int eg = tid >> 3;         // entry group:  entries eg*8 .. eg*8+7
    const int e0 = eg * 8;

    unsigned long long acc[8][4];
#pragma unroll
    for (int e = 0; e < 8; e++)
#pragma unroll
        for (int j = 0; j < 4; j++) acc[e][j] = 0ull;

#pragma unroll 2
    for (int k = 0; k < 64; k++) {
        const ulonglong2* w0p = (const ulonglong2*)(w0s + k * 64 + og * 8);
        const ulonglong2* w1p = (const ulonglong2*)(w1s + k * 64 + og * 8);
        ulonglong2 wa = w0p[0], wb = w0p[1];
        ulonglong2 va = w1p[0], vb = w1p[1];

        const float4* xp = (const float4*)(Xs  + k * 256 + e0);
        const float4* tp = (const float4*)(XTs + k * 256 + e0);
        float4 x0 = xp[0], x1 = xp[1];
        float4 t0 = tp[0], t1 = tp[1];
        float xv[8] = {x0.x, x0.y, x0.z, x0.w, x1.x, x1.y, x1.z, x1.w};
        float tv[8] = {t0.x, t0.y, t0.z, t0.w, t1.x, t1.y, t1.z, t1.w};

#pragma unroll
        for (int e = 0; e < 8; e++) {
            unsigned long long xx = pack_dup(xv[e]);
            unsigned long long tt = pack_dup(tv[e]);
            acc[e][0] = fma2(xx, wa.x, acc[e][0]);
            acc[e][1] = fma2(xx, wa.y, acc[e][1]);
            acc[e][2] = fma2(xx, wb.x, acc[e][2]);
            acc[e][3] = fma2(xx, wb.y, acc[e][3]);
            acc[e][0] = fma2(tt, va.x, acc[e][0]);
            acc[e][1] = fma2(tt, va.y, acc[e][1]);
            acc[e][2] = fma2(tt, vb.x, acc[e][2]);
            acc[e][3] = fma2(tt, vb.y, acc[e][3]);
        }
    }

    // --- epilogue: add Frow/Fcol (+G on diagonal), store ---
#pragma unroll
    for (int e = 0; e < 8; e++) {
        int t = e0 + e;
        int r = r0 + (t >> 4);
        int c = c0 + (t & 15);
        float res[8];
        unpack2(acc[e][0], res[0], res[1]);
        unpack2(acc[e][1], res[2], res[3]);
        unpack2(acc[e][2], res[4], res[5]);
        unpack2(acc[e][3], res[6], res[7]);

        const float* fr = g_Frow + r * 64 + og * 8;
        const float* fc = g_Fcol + c * 64 + og * 8;
#pragma unroll
        for (int o = 0; o < 8; o++) res[o] += fr[o] + fc[o];
        if (r == c) {
            const float* gp = g_G + r * 64 + og * 8;
#pragma unroll
            for (int o = 0; o < 8; o++) res[o] += gp[o];
        }
        float4* o4 = (float4*)(out + (((size_t)r * N_DIM + c) * 64 + og * 8));
        o4[0] = make_float4(res[0], res[1], res[2], res[3]);
        o4[1] = make_float4(res[4], res[5], res[6], res[7]);
    }
}

// ---------------- launch ----------------
extern "C" void kernel_launch(void* const* d_in, const int* in_sizes, int n_in,
                              void* d_out, int out_size) {
    const float* X = (const float*)d_in[0];   // input_layer [S, 64]
    const float* W = (const float*)d_in[1];   // weights     [15, 64, 64]
    float* out = (float*)d_out;

    (void)in_sizes; (void)n_in; (void)out_size;

    rowpool_kernel<<<N_DIM, 256>>>(X);
    colpool_kernel<<<N_DIM, 256>>>(X);
    allpool_kernel<<<1, 256>>>();
    combine_kernel<<<N_DIM, 64>>>(W);

    const int smem_bytes = (2 * 64 * 256 + 2 * 64 * 64) * (int)sizeof(float); // 160 KB
    cudaFuncSetAttribute(main_kernel, cudaFuncAttributeMaxDynamicSharedMemorySize, smem_bytes);
    dim3 grid(N_DIM / 16, N_DIM / 16);
    main_kernel<<<grid, 256, smem_bytes>>>(X, W, out);
}

// round 2
// speedup vs baseline: 1.0000x; 1.0000x over previous
#include <cuda_runtime.h>
#include <cuda_bf16.h>
#include <cstdint>

#define N_DIM   1024
#define K_DIM   64
#define OUT_DIM 64

// ---------------- device scratch (no allocation allowed) ----------------
__device__ float g_CP[N_DIM * K_DIM];     // row means   (reference "col_pool")
__device__ float g_RP[N_DIM * K_DIM];     // column means (reference "row_pool")
__device__ float g_D [N_DIM * K_DIM];     // diagonal rows X[i,i,:]
__device__ float g_Pall [K_DIM];
__device__ float g_Pdiag[K_DIM];
__device__ float g_Frow[N_DIM * OUT_DIM];
__device__ float g_Fcol[N_DIM * OUT_DIM];
__device__ float g_G   [N_DIM * OUT_DIM];

// ---------------- packed f32x2 helpers ----------------
__device__ __forceinline__ unsigned long long pack_dup(float x) {
    unsigned long long r;
    asm("mov.b64 %0, {%1, %1};" : "=l"(r) : "f"(x));
    return r;
}
__device__ __forceinline__ unsigned long long fma2(unsigned long long a,
                                                   unsigned long long b,
                                                   unsigned long long c) {
    unsigned long long d;
    asm("fma.rn.f32x2 %0, %1, %2, %3;" : "=l"(d) : "l"(a), "l"(b), "l"(c));
    return d;
}
__device__ __forceinline__ void unpack2(unsigned long long v, float& lo, float& hi) {
    asm("mov.b64 {%0, %1}, %2;" : "=f"(lo), "=f"(hi) : "l"(v));
}

// ---------------- pooling kernels ----------------
// CP[i] = mean over c of X[i*N + c]  ; D[i] = X[i*N + i]
__global__ __launch_bounds__(256) void rowpool_kernel(const float* __restrict__ X) {
    int i   = blockIdx.x;
    int tid = threadIdx.x;
    int c4  = tid >> 6;          // 0..3
    int k   = tid & 63;
    const float* base = X + (size_t)i * N_DIM * K_DIM;
    float s = 0.f;
#pragma unroll 4
    for (int c = c4; c < N_DIM; c += 4) s += base[c * K_DIM + k];
    __shared__ float red[256];
    red[tid] = s;
    __syncthreads();
    if (c4 == 0) {
        float v = red[k] + red[64 + k] + red[128 + k] + red[192 + k];
        g_CP[i * K_DIM + k] = v * (1.0f / N_DIM);
        g_D [i * K_DIM + k] = base[i * K_DIM + k];
    }
}

// RP[j] = mean over r of X[r*N + j]
__global__ __launch_bounds__(256) void colpool_kernel(const float* __restrict__ X) {
    int j   = blockIdx.x;
    int tid = threadIdx.x;
    int r4  = tid >> 6;
    int k   = tid & 63;
    float s = 0.f;
#pragma unroll 4
    for (int r = r4; r < N_DIM; r += 4)
        s += X[((size_t)r * N_DIM + j) * K_DIM + k];
    __shared__ float red[256];
    red[tid] = s;
    __syncthreads();
    if (r4 == 0) {
        float v = red[k] + red[64 + k] + red[128 + k] + red[192 + k];
        g_RP[j * K_DIM + k] = v * (1.0f / N_DIM);
    }
}

// Pall[k] = mean_i CP[i][k] ; Pdiag[k] = mean_i D[i][k]
__global__ __launch_bounds__(256) void allpool_kernel() {
    int tid = threadIdx.x;
    int i4  = tid >> 6;
    int k   = tid & 63;
    float sa = 0.f, sd = 0.f;
#pragma unroll 4
    for (int i = i4; i < N_DIM; i += 4) {
        sa += g_CP[i * K_DIM + k];
        sd += g_D [i * K_DIM + k];
    }
    __shared__ float ra[256], rd[256];
    ra[tid] = sa; rd[tid] = sd;
    __syncthreads();
    if (i4 == 0) {
        g_Pall [k] = (ra[k] + ra[64 + k] + ra[128 + k] + ra[192 + k]) * (1.0f / N_DIM);
        g_Pdiag[k] = (rd[k] + rd[64 + k] + rd[128 + k] + rd[192 + k]) * (1.0f / N_DIM);
    }
}

// ---------------- per-row/col feature combine (tiny GEMMs) ----------------
__global__ __launch_bounds__(64) void combine_kernel(const float* __restrict__ W) {
    int i = blockIdx.x;
    int o = threadIdx.x;
    __shared__ float rp[64], cp[64], dd[64], pa[64], pd[64];
    rp[o] = g_RP[i * 64 + o];
    cp[o] = g_CP[i * 64 + o];
    dd[o] = g_D [i * 64 + o];
    pa[o] = g_Pall[o];
    pd[o] = g_Pdiag[o];
    __syncthreads();

    float fr = 0.f, fc = 0.f, gg = 0.f;
#pragma unroll 4
    for (int k = 0; k < 64; k++) {
        float rpk = rp[k], cpk = cp[k], ddk = dd[k], pak = pa[k], pdk = pd[k];
        // W layout: W[w][k][o] = W[(w*64 + k)*64 + o]
        fr += rpk * W[(4 * 64 + k) * 64 + o];
        fr += cpk * W[(5 * 64 + k) * 64 + o];
        fr += ddk * W[(14 * 64 + k) * 64 + o];
        fr += pak * W[(7 * 64 + k) * 64 + o];
        fr += pdk * W[(12 * 64 + k) * 64 + o];

        fc += rpk * W[(3 * 64 + k) * 64 + o];
        fc += cpk * W[(6 * 64 + k) * 64 + o];
        fc += ddk * W[(13 * 64 + k) * 64 + o];

        gg += ddk * W[(2 * 64 + k) * 64 + o];
        gg += rpk * W[(10 * 64 + k) * 64 + o];
        gg += cpk * W[(11 * 64 + k) * 64 + o];
        gg += pak * W[(9 * 64 + k) * 64 + o];
        gg += pdk * W[(8 * 64 + k) * 64 + o];
    }
    g_Frow[i * 64 + o] = fr;
    g_Fcol[i * 64 + o] = fc;
    g_G   [i * 64 + o] = gg;
}

// ---------------- main fused pass ----------------
// out[(r,c)] = X[(r,c)]@W0 + X[(c,r)]@W1 + Frow[r] + Fcol[c] + [r==c]*G[r]
// Tile: 16x16 entries (256), 256 threads, per-thread 8 entries x 8 outputs.
// Dynamic smem: Xs[64][256], XTs[64][256], W0s[64][64], W1s[64][64] = 160 KB.
__global__ __launch_bounds__(256, 1) void main_kernel(const float* __restrict__ X,
                                                      const float* __restrict__ W,
                                                      float* __restrict__ out) {
    extern __shared__ float sm[];
    float* Xs  = sm;                 // [k][t]   64*256
    float* XTs = sm + 64 * 256;      // [k][t]
    float* w0s = sm + 2 * 64 * 256;  // [k][o]   64*64
    float* w1s = w0s + 64 * 64;

    const int tid = threadIdx.x;
    const int r0 = blockIdx.y * 16;
    const int c0 = blockIdx.x * 16;

    // --- stage W0, W1 ---
    {
        const float4* w0g = (const float4*)W;                  // W[0]
        const float4* w1g = (const float4*)(W + 64 * 64);      // W[1]
        float4* d0 = (float4*)w0s;
        float4* d1 = (float4*)w1s;
#pragma unroll
        for (int idx = tid; idx < 1024; idx += 256) {
            d0[idx] = w0g[idx];
            d1[idx] = w1g[idx];
        }
    }

    // --- stage X tile (direct) and X^T tile ---
    {
        int t  = tid;                 // one entry per thread
        int er = t >> 4, ec = t & 15;
        size_t s  = ((size_t)(r0 + er) * N_DIM + (c0 + ec)) * K_DIM;
        size_t st = ((size_t)(c0 + ec) * N_DIM + (r0 + er)) * K_DIM;
        const float4* xs4 = (const float4*)(X + s);
        const float4* xt4 = (const float4*)(X + st);
#pragma unroll
        for (int kq = 0; kq < 16; kq++) {
            float4 v  = xs4[kq];
            float4 vt = xt4[kq];
            int kb = kq * 4;
            Xs [(kb + 0) * 256 + t] = v.x;  Xs [(kb + 1) * 256 + t] = v.y;
            Xs [(kb + 2) * 256 + t] = v.z;  Xs [(kb + 3) * 256 + t] = v.w;
            XTs[(kb + 0) * 256 + t] = vt.x; XTs[(kb + 1) * 256 + t] = vt.y;
            XTs[(kb + 2) * 256 + t] = vt.z; XTs[(kb + 3) * 256 + t] = vt.w;
        }
    }
    __syncthreads();

    // --- register-tiled compute: 8 entries x 8 outputs, packed f32x2 ---
    const int og = tid & 7;          // output group: outputs og*8 .. og*8+7
    const int eg = tid >> 3;         // entry group:  entries eg*8 .. eg*8+7
    const int e0 = eg * 8;

    unsigned long long acc[8][4];
#pragma unroll
    for (int e = 0; e < 8; e++)
#pragma unroll
        for (int j = 0; j < 4; j++) acc[e][j] = 0ull;

#pragma unroll 2
    for (int k = 0; k < 64; k++) {
        const ulonglong2* w0p = (const ulonglong2*)(w0s + k * 64 + og * 8);
        const ulonglong2* w1p = (const ulonglong2*)(w1s + k * 64 + og * 8);
        ulonglong2 wa = w0p[0], wb = w0p[1];
        ulonglong2 va = w1p[0], vb = w1p[1];

        const float4* xp = (const float4*)(Xs  + k * 256 + e0);
        const float4* tp = (const float4*)(XTs + k * 256 + e0);
        float4 x0 = xp[0], x1 = xp[1];
        float4 t0 = tp[0], t1 = tp[1];
        float xv[8] = {x0.x, x0.y, x0.z, x0.w, x1.x, x1.y, x1.z, x1.w};
        float tv[8] = {t0.x, t0.y, t0.z, t0.w, t1.x, t1.y, t1.z, t1.w};

#pragma unroll
        for (int e = 0; e < 8; e++) {
            unsigned long long xx = pack_dup(xv[e]);
            unsigned long long tt = pack_dup(tv[e]);
            acc[e][0] = fma2(xx, wa.x, acc[e][0]);
            acc[e][1] = fma2(xx, wa.y, acc[e][1]);
            acc[e][2] = fma2(xx, wb.x, acc[e][2]);
            acc[e][3] = fma2(xx, wb.y, acc[e][3]);
            acc[e][0] = fma2(tt, va.x, acc[e][0]);
            acc[e][1] = fma2(tt, va.y, acc[e][1]);
            acc[e][2] = fma2(tt, vb.x, acc[e][2]);
            acc[e][3] = fma2(tt, vb.y, acc[e][3]);
        }
    }

    // --- epilogue: add Frow/Fcol (+G on diagonal), store ---
#pragma unroll
    for (int e = 0; e < 8; e++) {
        int t = e0 + e;
        int r = r0 + (t >> 4);
        int c = c0 + (t & 15);
        float res[8];
        unpack2(acc[e][0], res[0], res[1]);
        unpack2(acc[e][1], res[2], res[3]);
        unpack2(acc[e][2], res[4], res[5]);
        unpack2(acc[e][3], res[6], res[7]);

        const float* fr = g_Frow + r * 64 + og * 8;
        const float* fc = g_Fcol + c * 64 + og * 8;
#pragma unroll
        for (int o = 0; o < 8; o++) res[o] += fr[o] + fc[o];
        if (r == c) {
            const float* gp = g_G + r * 64 + og * 8;
#pragma unroll
            for (int o = 0; o < 8; o++) res[o] += gp[o];
        }
        float4* o4 = (float4*)(out + (((size_t)r * N_DIM + c) * 64 + og * 8));
        o4[0] = make_float4(res[0], res[1], res[2], res[3]);
        o4[1] = make_float4(res[4], res[5], res[6], res[7]);
    }
}

// ---------------- launch ----------------
extern "C" void kernel_launch(void* const* d_in, const int* in_sizes, int n_in,
                              void* d_out, int out_size) {
    const float* X = (const float*)d_in[0];   // input_layer [S, 64]
    const float* W = (const float*)d_in[1];   // weights     [15, 64, 64]
    float* out = (float*)d_out;

    (void)in_sizes; (void)n_in; (void)out_size;

    rowpool_kernel<<<N_DIM, 256>>>(X);
    colpool_kernel<<<N_DIM, 256>>>(X);
    allpool_kernel<<<1, 256>>>();
    combine_kernel<<<N_DIM, 64>>>(W);

    const int smem_bytes = (2 * 64 * 256 + 2 * 64 * 64) * (int)sizeof(float); // 160 KB
    cudaFuncSetAttribute(main_kernel, cudaFuncAttributeMaxDynamicSharedMemorySize, smem_bytes);
    dim3 grid(N_DIM / 16, N_DIM / 16);
    main_kernel<<<grid, 256, smem_bytes>>>(X, W, out);
}

// round 5
// speedup vs baseline: 1.6563x; 1.6562x over previous
#include <cuda_runtime.h>
#include <cstdint>
#include <cmath>

#define N_DIM   1024
#define K_DIM   64
#define OUT_DIM 64
#define NPAIR   2080   // 64*65/2 tile pairs (16x16 entry tiles)

// ---------------- device scratch ----------------
__device__ float g_CP[N_DIM * K_DIM];     // row means of big matrix  (ref "col_pool")
__device__ float g_RP[N_DIM * K_DIM];     // column means             (ref "row_pool")
__device__ float g_D [N_DIM * K_DIM];     // diagonal rows X[i,i,:]
__device__ float g_Pall [K_DIM];
__device__ float g_Pdiag[K_DIM];
__device__ float g_Frow[N_DIM * OUT_DIM];
__device__ float g_Fcol[N_DIM * OUT_DIM];
__device__ float g_G   [N_DIM * OUT_DIM];

// ---------------- helpers ----------------
__device__ __forceinline__ uint32_t f2tf(float x) {
    uint32_t u;
    asm("cvt.rna.tf32.f32 %0, %1;" : "=r"(u) : "f"(x));
    return u;
}

__device__ __forceinline__ void mma_tf32(float* d, const uint32_t* a, const uint32_t* b) {
    asm volatile(
        "mma.sync.aligned.m16n8k8.row.col.f32.tf32.tf32.f32 "
        "{%0,%1,%2,%3}, {%4,%5,%6,%7}, {%8,%9}, {%0,%1,%2,%3};"
        : "+f"(d[0]), "+f"(d[1]), "+f"(d[2]), "+f"(d[3])
        : "r"(a[0]), "r"(a[1]), "r"(a[2]), "r"(a[3]), "r"(b[0]), "r"(b[1]));
}

// ---------------- pooling kernels (unchanged, known-correct) ----------------
__global__ __launch_bounds__(256) void rowpool_kernel(const float* __restrict__ X) {
    int i   = blockIdx.x;
    int tid = threadIdx.x;
    int c4  = tid >> 6;
    int k   = tid & 63;
    const float* base = X + (size_t)i * N_DIM * K_DIM;
    float s = 0.f;
#pragma unroll 4
    for (int c = c4; c < N_DIM; c += 4) s += base[c * K_DIM + k];
    __shared__ float red[256];
    red[tid] = s;
    __syncthreads();
    if (c4 == 0) {
        float v = red[k] + red[64 + k] + red[128 + k] + red[192 + k];
        g_CP[i * K_DIM + k] = v * (1.0f / N_DIM);
        g_D [i * K_DIM + k] = base[i * K_DIM + k];
    }
}

__global__ __launch_bounds__(256) void colpool_kernel(const float* __restrict__ X) {
    int j   = blockIdx.x;
    int tid = threadIdx.x;
    int r4  = tid >> 6;
    int k   = tid & 63;
    float s = 0.f;
#pragma unroll 4
    for (int r = r4; r < N_DIM; r += 4)
        s += X[((size_t)r * N_DIM + j) * K_DIM + k];
    __shared__ float red[256];
    red[tid] = s;
    __syncthreads();
    if (r4 == 0) {
        float v = red[k] + red[64 + k] + red[128 + k] + red[192 + k];
        g_RP[j * K_DIM + k] = v * (1.0f / N_DIM);
    }
}

__global__ __launch_bounds__(256) void allpool_kernel() {
    int tid = threadIdx.x;
    int i4  = tid >> 6;
    int k   = tid & 63;
    float sa = 0.f, sd = 0.f;
#pragma unroll 4
    for (int i = i4; i < N_DIM; i += 4) {
        sa += g_CP[i * K_DIM + k];
        sd += g_D [i * K_DIM + k];
    }
    __shared__ float ra[256], rd[256];
    ra[tid] = sa; rd[tid] = sd;
    __syncthreads();
    if (i4 == 0) {
        g_Pall [k] = (ra[k] + ra[64 + k] + ra[128 + k] + ra[192 + k]) * (1.0f / N_DIM);
        g_Pdiag[k] = (rd[k] + rd[64 + k] + rd[128 + k] + rd[192 + k]) * (1.0f / N_DIM);
    }
}

// ---------------- combine: Frow/Fcol/G via smem-staged weights ----------------
// 64 blocks x 256 threads, each block handles 16 i-rows.
__global__ __launch_bounds__(256) void combine2_kernel(const float* __restrict__ W) {
    extern __shared__ float cs[];
    float* sW9 = cs;               // 9*4096
    float* sRP = sW9 + 9 * 4096;   // 16*64
    float* sCP = sRP + 1024;
    float* sD  = sCP + 1024;
    float* cF  = sD  + 1024;       // 64
    float* cG  = cF  + 64;         // 64

    int t  = threadIdx.x;
    int i0 = blockIdx.x * 16;
    // mats order: Frow{4,5,14}, Fcol{3,6,13}, G{2,10,11}
#pragma unroll
    for (int m = 0; m < 9; m++) {
        const int mats[9] = {4, 5, 14, 3, 6, 13, 2, 10, 11};
        for (int idx = t; idx < 4096; idx += 256)
            sW9[m * 4096 + idx] = W[mats[m] * 4096 + idx];
    }
    for (int idx = t; idx < 1024; idx += 256) {
        sRP[idx] = g_RP[i0 * 64 + idx];
        sCP[idx] = g_CP[i0 * 64 + idx];
        sD [idx] = g_D [i0 * 64 + idx];
    }
    if (t < 64) {
        float f = 0.f, g = 0.f;
#pragma unroll 8
        for (int k = 0; k < 64; k++) {
            float pa = g_Pall[k], pd = g_Pdiag[k];
            f += pa * W[(7 * 64 + k) * 64 + t] + pd * W[(12 * 64 + k) * 64 + t];
            g += pa * W[(9 * 64 + k) * 64 + t] + pd * W[(8  * 64 + k) * 64 + t];
        }
        cF[t] = f; cG[t] = g;
    }
    __syncthreads();

    int o  = t & 63;
    int ig = t >> 6;
#pragma unroll
    for (int r = 0; r < 4; r++) {
        int li = ig * 4 + r;
        float fr = cF[o], fc = 0.f, gg = cG[o];
#pragma unroll 8
        for (int k = 0; k < 64; k++) {
            float rp = sRP[li * 64 + k], cp = sCP[li * 64 + k], dd = sD[li * 64 + k];
            fr += rp * sW9[0 * 4096 + k * 64 + o] + cp * sW9[1 * 4096 + k * 64 + o] + dd * sW9[2 * 4096 + k * 64 + o];
            fc += rp * sW9[3 * 4096 + k * 64 + o] + cp * sW9[4 * 4096 + k * 64 + o] + dd * sW9[5 * 4096 + k * 64 + o];
            gg += dd * sW9[6 * 4096 + k * 64 + o] + rp * sW9[7 * 4096 + k * 64 + o] + cp * sW9[8 * 4096 + k * 64 + o];
        }
        g_Frow[(i0 + li) * 64 + o] = fr;
        g_Fcol[(i0 + li) * 64 + o] = fc;
        g_G  [(i0 + li) * 64 + o]  = gg;
    }
}

// ---------------- main pass: tf32 mma, pair-tiled ----------------
// Block p handles tile pair {I,J} (I>=J), 16x16 entries per tile.
// O1[e=(lr,lc)] = A[e]@W0 + B[T(e)]@W1 ; O2[f] = B[f]@W0 + A[T(f)]@W1
// where A = X[16I+lr, 16J+lc], B = X[16J+lr, 16I+lc], T(e) = ((e&15)<<4)|(e>>4).
__global__ __launch_bounds__(256, 1) void main_mma_kernel(const float* __restrict__ X,
                                                          const float* __restrict__ Wg,
                                                          float* __restrict__ out) {
    extern __shared__ float sm[];
    uint32_t* sA   = (uint32_t*)sm;          // 16384 (tf32 bits), swizzled
    uint32_t* sB   = sA + 16384;             // 16384
    float*    sW   = (float*)(sB + 16384);   // 8192 frag-packed (tf32 bits)
    float*    sFrI = sW + 8192;              // 1024
    float*    sFrJ = sFrI + 1024;            // 1024
    float*    sFcI = sFrJ + 1024;            // 16*66
    float*    sFcJ = sFcI + 1056;            // 16*66
    float*    sG   = sFcJ + 1056;            // 1024

    const int tid = threadIdx.x;
    const int p   = blockIdx.x;

    // triangular pair decode: I >= J
    int I = (int)((sqrtf(8.0f * (float)p + 1.0f) - 0.999f) * 0.5f);
    while ((I + 1) * (I + 2) / 2 <= p) ++I;
    while (I * (I + 1) / 2 > p) --I;
    const int J = p - I * (I + 1) / 2;

    const int r0 = I * 16, c0 = J * 16;

    // --- stage X tiles (tf32-converted, swizzled) ---
    const float4* Xv = (const float4*)X;
#pragma unroll
    for (int q = 0; q < 16; q++) {
        int v  = q * 256 + tid;      // float4 index within tile
        int e  = v >> 4;             // entry 0..255
        int kq = v & 15;             // 4-float group
        int lr = e >> 4, lc = e & 15;
        float4 a4 = Xv[((size_t)(r0 + lr) * N_DIM + (c0 + lc)) * 16 + kq];
        float4 b4 = Xv[((size_t)(c0 + lr) * N_DIM + (r0 + lc)) * 16 + kq];
        int swz = (e ^ (e >> 4)) & 7;
        int off = e * 64 + ((kq ^ swz) << 2);
        *(uint4*)(sA + off) = make_uint4(f2tf(a4.x), f2tf(a4.y), f2tf(a4.z), f2tf(a4.w));
        *(uint4*)(sB + off) = make_uint4(f2tf(b4.x), f2tf(b4.y), f2tf(b4.z), f2tf(b4.w));
    }

    // --- stage W0/W1 in mma-fragment order: [(ph*8+kk)*8+nt][lane] -> float2 ---
    for (int idx = tid; idx < 4096; idx += 256) {
        int lane = idx & 31, nt = (idx >> 5) & 7, kk = (idx >> 8) & 7, ph = idx >> 11;
        int k0 = kk * 8 + (lane & 3);
        int n  = nt * 8 + (lane >> 2);
        uint2 uu = make_uint2(f2tf(Wg[(ph * 64 + k0) * 64 + n]),
                              f2tf(Wg[(ph * 64 + k0 + 4) * 64 + n]));
        *(uint2*)(sW + idx * 2) = uu;
    }

    // --- stage broadcast features ---
    for (int idx = tid; idx < 1024; idx += 256) {
        int rr = idx >> 6, o = idx & 63;
        sFrI[idx] = g_Frow[(r0 + rr) * 64 + o];
        sFrJ[idx] = g_Frow[(c0 + rr) * 64 + o];
        sFcI[rr * 66 + o] = g_Fcol[(r0 + rr) * 64 + o];
        sFcJ[rr * 66 + o] = g_Fcol[(c0 + rr) * 64 + o];
        sG[idx] = g_G[(r0 + rr) * 64 + o];
    }
    __syncthreads();

    // --- compute ---
    const int warp = tid >> 5, lane = tid & 31;
    const int half = warp >> 2;           // 0: O1, 1: O2
    const int wm   = warp & 3;
    const uint32_t* srcN = half ? sB : sA;   // phase 0 (W0): natural order
    const uint32_t* srcT = half ? sA : sB;   // phase 1 (W1): transposed order
    const int rA = lane >> 2;             // 0..7
    const int cA = lane & 3;

    float acc[4][8][4];
#pragma unroll
    for (int m = 0; m < 4; m++)
#pragma unroll
        for (int n = 0; n < 8; n++)
#pragma unroll
            for (int j = 0; j < 4; j++) acc[m][n][j] = 0.f;

#pragma unroll
    for (int kt = 0; kt < 16; kt++) {
        const int ph = kt >> 3, kk = kt & 7;
        const int kb = kk * 8 + cA;
        const uint32_t* s = ph ? srcT : srcN;

        uint32_t a[4][4];
#pragma unroll
        for (int m = 0; m < 4; m++) {
            int mt = wm * 4 + m;
#pragma unroll
            for (int hh = 0; hh < 2; hh++) {
                int e  = mt * 16 + rA + hh * 8;
                int ee = ph ? (((e & 15) << 4) | (e >> 4)) : e;
                int sw = ((ee ^ (ee >> 4)) & 7) << 2;
                a[m][hh]     = s[ee * 64 + (kb ^ sw)];
                a[m][hh + 2] = s[ee * 64 + ((kb + 4) ^ sw)];
            }
        }

        uint32_t b[8][2];
#pragma unroll
        for (int nt = 0; nt < 8; nt++) {
            uint2 w2 = *(const uint2*)(sW + (((ph * 8 + kk) * 8 + nt) * 32 + lane) * 2);
            b[nt][0] = w2.x; b[nt][1] = w2.y;
        }

#pragma unroll
        for (int m = 0; m < 4; m++)
#pragma unroll
            for (int nt = 0; nt < 8; nt++)
                mma_tf32(acc[m][nt], a[m], b[nt]);
    }

    // --- epilogue ---
    const int tI = half ? J : I;          // output row-tile
    const int tJ = half ? I : J;          // output col-tile
    const float* Fr = half ? sFrJ : sFrI;
    const float* Fc = half ? sFcI : sFcJ;
    const bool diagBlk = (I == J);
    const int c2 = (lane & 3) * 2;

#pragma unroll
    for (int nt = 0; nt < 8; nt++) {
        float2 fc0 = *(const float2*)(Fc + rA * 66 + nt * 8 + c2);
        float2 fc1 = *(const float2*)(Fc + (rA + 8) * 66 + nt * 8 + c2);
#pragma unroll
        for (int m = 0; m < 4; m++) {
            int mt = wm * 4 + m;
            float2 fr = *(const float2*)(Fr + mt * 64 + nt * 8 + c2);
            float v0 = acc[m][nt][0] + fr.x + fc0.x;
            float v1 = acc[m][nt][1] + fr.y + fc0.y;
            float v2 = acc[m][nt][2] + fr.x + fc1.x;
            float v3 = acc[m][nt][3] + fr.y + fc1.y;
            if (diagBlk) {
                if (mt == rA)     { v0 += sG[mt * 64 + nt * 8 + c2]; v1 += sG[mt * 64 + nt * 8 + c2 + 1]; }
                if (mt == rA + 8) { v2 += sG[mt * 64 + nt * 8 + c2]; v3 += sG[mt * 64 + nt * 8 + c2 + 1]; }
            }
            size_t base = ((size_t)(tI * 16 + mt) * N_DIM + tJ * 16 + rA) * 64 + nt * 8 + c2;
            *(float2*)(out + base)           = make_float2(v0, v1);
            *(float2*)(out + base + 8 * 64)  = make_float2(v2, v3);
        }
    }
}

// ---------------- launch ----------------
extern "C" void kernel_launch(void* const* d_in, const int* in_sizes, int n_in,
                              void* d_out, int out_size) {
    const float* X = (const float*)d_in[0];   // [S, 64]
    const float* W = (const float*)d_in[1];   // [15, 64, 64]
    float* out = (float*)d_out;
    (void)in_sizes; (void)n_in; (void)out_size;

    rowpool_kernel<<<N_DIM, 256>>>(X);
    colpool_kernel<<<N_DIM, 256>>>(X);
    allpool_kernel<<<1, 256>>>();

    const int combine_smem = (9 * 4096 + 3 * 1024 + 128) * (int)sizeof(float); // ~160KB
    cudaFuncSetAttribute(combine2_kernel, cudaFuncAttributeMaxDynamicSharedMemorySize, combine_smem);
    combine2_kernel<<<64, 256, combine_smem>>>(W);

    const int main_smem = (2 * 16384 + 8192 + 2 * 1024 + 2 * 1056 + 1024) * (int)sizeof(float); // ~180KB
    cudaFuncSetAttribute(main_mma_kernel, cudaFuncAttributeMaxDynamicSharedMemorySize, main_smem);
    main_mma_kernel<<<NPAIR, 256, main_smem>>>(X, W, out);
}

// round 6
// speedup vs baseline: 1.6772x; 1.0126x over previous
#include <cuda_runtime.h>
#include <cstdint>
#include <cmath>

#define N_DIM   1024
#define K_DIM   64
#define OUT_DIM 64
#define NPAIR   2080   // 64*65/2 tile pairs (16x16 entry tiles)

// ---------------- device scratch ----------------
__device__ float g_CP[N_DIM * K_DIM];     // row means   (ref "col_pool")
__device__ float g_RP[N_DIM * K_DIM];     // column means (ref "row_pool")
__device__ float g_D [N_DIM * K_DIM];     // diagonal rows X[i,i,:]
__device__ float g_Frow[N_DIM * OUT_DIM];
__device__ float g_Fcol[N_DIM * OUT_DIM];
__device__ float g_G   [N_DIM * OUT_DIM];

// ---------------- helpers ----------------
__device__ __forceinline__ uint32_t f2tf(float x) {
    uint32_t u;
    asm("cvt.rna.tf32.f32 %0, %1;" : "=r"(u) : "f"(x));
    return u;
}

__device__ __forceinline__ void mma_tf32(float* d, const uint32_t* a, const uint32_t* b) {
    asm volatile(
        "mma.sync.aligned.m16n8k8.row.col.f32.tf32.tf32.f32 "
        "{%0,%1,%2,%3}, {%4,%5,%6,%7}, {%8,%9}, {%0,%1,%2,%3};"
        : "+f"(d[0]), "+f"(d[1]), "+f"(d[2]), "+f"(d[3])
        : "r"(a[0]), "r"(a[1]), "r"(a[2]), "r"(a[3]), "r"(b[0]), "r"(b[1]));
}

// ---------------- pooling kernels ----------------
__global__ __launch_bounds__(256) void rowpool_kernel(const float* __restrict__ X) {
    int i   = blockIdx.x;
    int tid = threadIdx.x;
    int c4  = tid >> 6;
    int k   = tid & 63;
    const float* base = X + (size_t)i * N_DIM * K_DIM;
    float s = 0.f;
#pragma unroll 4
    for (int c = c4; c < N_DIM; c += 4) s += base[c * K_DIM + k];
    __shared__ float red[256];
    red[tid] = s;
    __syncthreads();
    if (c4 == 0) {
        float v = red[k] + red[64 + k] + red[128 + k] + red[192 + k];
        g_CP[i * K_DIM + k] = v * (1.0f / N_DIM);
        g_D [i * K_DIM + k] = base[i * K_DIM + k];
    }
}

__global__ __launch_bounds__(256) void colpool_kernel(const float* __restrict__ X) {
    int j   = blockIdx.x;
    int tid = threadIdx.x;
    int r4  = tid >> 6;
    int k   = tid & 63;
    float s = 0.f;
#pragma unroll 4
    for (int r = r4; r < N_DIM; r += 4)
        s += X[((size_t)r * N_DIM + j) * K_DIM + k];
    __shared__ float red[256];
    red[tid] = s;
    __syncthreads();
    if (r4 == 0) {
        float v = red[k] + red[64 + k] + red[128 + k] + red[192 + k];
        g_RP[j * K_DIM + k] = v * (1.0f / N_DIM);
    }
}

// ---------------- combine: Frow/Fcol/G, Pall/Pdiag folded in ----------------
// 256 blocks x 256 threads, block handles 4 i-rows. Weights read through L2.
__global__ __launch_bounds__(256) void combine3_kernel(const float* __restrict__ W) {
    __shared__ float red[2][256];
    __shared__ float sPall[64], sPdiag[64], cF[64], cG[64];
    __shared__ float feat[12][64];   // [arr(RP,CP,D)*4 + li][k]
    int t  = threadIdx.x;
    int i0 = blockIdx.x * 4;

    // phase 1: partial sums for Pall/Pdiag (redundant per block; L2-hot)
    int k = t & 63, seg = t >> 6;
    {
        const float* cpb = g_CP + (size_t)(seg * 256) * 64 + k;
        const float* db  = g_D  + (size_t)(seg * 256) * 64 + k;
        float sa = 0.f, sd = 0.f;
#pragma unroll 16
        for (int i = 0; i < 256; i++) { sa += cpb[i * 64]; sd += db[i * 64]; }
        red[0][t] = sa; red[1][t] = sd;
    }
    // stage this block's 4 rows of RP/CP/D
    for (int idx = t; idx < 768; idx += 256) {
        int arr = idx >> 8; int rem = idx & 255; int li = rem >> 6; int o = rem & 63;
        const float* src = (arr == 0) ? g_RP : ((arr == 1) ? g_CP : g_D);
        feat[arr * 4 + li][o] = src[(i0 + li) * 64 + o];
    }
    __syncthreads();
    if (t < 64) {
        sPall [t] = (red[0][t] + red[0][64 + t] + red[0][128 + t] + red[0][192 + t]) * (1.0f / 1024.0f);
        sPdiag[t] = (red[1][t] + red[1][64 + t] + red[1][128 + t] + red[1][192 + t]) * (1.0f / 1024.0f);
    }
    __syncthreads();
    if (t < 64) {
        float f = 0.f, g = 0.f;
#pragma unroll 8
        for (int kk = 0; kk < 64; kk++) {
            float pa = sPall[kk], pd = sPdiag[kk];
            f += pa * W[(7 * 64 + kk) * 64 + t] + pd * W[(12 * 64 + kk) * 64 + t];
            g += pa * W[(9 * 64 + kk) * 64 + t] + pd * W[(8  * 64 + kk) * 64 + t];
        }
        cF[t] = f; cG[t] = g;
    }
    __syncthreads();

    int o = t & 63, li = t >> 6;
    float fr = cF[o], fc = 0.f, gg = cG[o];
#pragma unroll 8
    for (int kk = 0; kk < 64; kk++) {
        float rp = feat[0 + li][kk], cp = feat[4 + li][kk], dd = feat[8 + li][kk];
        fr += rp * W[(4 * 64 + kk) * 64 + o] + cp * W[(5 * 64 + kk) * 64 + o] + dd * W[(14 * 64 + kk) * 64 + o];
        fc += rp * W[(3 * 64 + kk) * 64 + o] + cp * W[(6 * 64 + kk) * 64 + o] + dd * W[(13 * 64 + kk) * 64 + o];
        gg += dd * W[(2 * 64 + kk) * 64 + o] + rp * W[(10 * 64 + kk) * 64 + o] + cp * W[(11 * 64 + kk) * 64 + o];
    }
    g_Frow[(i0 + li) * 64 + o] = fr;
    g_Fcol[(i0 + li) * 64 + o] = fc;
    g_G  [(i0 + li) * 64 + o]  = gg;
}

// ---------------- main pass: tf32 mma, pair-tiled, cp.async k-half pipeline ----
// Block p handles tile pair {I,J} (I>=J), 16x16 entries per tile.
// sA/sB hold raw fp32 bits, [kh][entry e][k 0..31] with XOR swizzle; tf32 cvt at
// fragment-load time. Two cp.async commit groups (k-halves) overlap DRAM with MMA.
__global__ __launch_bounds__(256, 1) void main_mma_kernel(const float* __restrict__ X,
                                                          const float* __restrict__ Wg,
                                                          float* __restrict__ out) {
    extern __shared__ float smf[];
    uint32_t* sA   = (uint32_t*)smf;         // 2*256*32 raw f32 bits
    uint32_t* sB   = sA + 16384;             // 2*256*32
    float*    sW   = (float*)(sB + 16384);   // 8192 frag-packed tf32 bits
    float*    sFrI = sW + 8192;              // 1024
    float*    sFrJ = sFrI + 1024;            // 1024
    float*    sFcI = sFrJ + 1024;            // 16*66
    float*    sFcJ = sFcI + 1056;            // 16*66
    float*    sG   = sFcJ + 1056;            // 1024

    const int tid = threadIdx.x;
    const int p   = blockIdx.x;

    // triangular pair decode: I >= J
    int I = (int)((sqrtf(8.0f * (float)p + 1.0f) - 0.999f) * 0.5f);
    while ((I + 1) * (I + 2) / 2 <= p) ++I;
    while (I * (I + 1) / 2 > p) --I;
    const int J = p - I * (I + 1) / 2;
    const int r0 = I * 16, c0 = J * 16;

    // --- issue cp.async staging of X (two k-half groups) ---
    {
        uint32_t aA = (uint32_t)__cvta_generic_to_shared(sA);
        uint32_t aB = (uint32_t)__cvta_generic_to_shared(sB);
#pragma unroll
        for (int kh = 0; kh < 2; kh++) {
#pragma unroll
            for (int q = 0; q < 8; q++) {
                int v  = q * 256 + tid;
                int e  = v >> 3;          // entry 0..255
                int kq = v & 7;           // float4 group within half
                int lr = e >> 4, lc = e & 15;
                int swz = (e ^ (e >> 4)) & 7;
                uint32_t off = (uint32_t)(e * 32 + ((kq ^ swz) << 2)) * 4u + (uint32_t)kh * 32768u;
                const float* srcA = X + ((size_t)(r0 + lr) * N_DIM + (c0 + lc)) * 64 + kh * 32 + kq * 4;
                const float* srcB = X + ((size_t)(c0 + lr) * N_DIM + (r0 + lc)) * 64 + kh * 32 + kq * 4;
                asm volatile("cp.async.cg.shared.global [%0], [%1], 16;" :: "r"(aA + off), "l"(srcA));
                asm volatile("cp.async.cg.shared.global [%0], [%1], 16;" :: "r"(aB + off), "l"(srcB));
            }
            asm volatile("cp.async.commit_group;");
        }
    }

    // --- stage W0/W1 in mma-fragment order ---
    for (int idx = tid; idx < 4096; idx += 256) {
        int lane = idx & 31, nt = (idx >> 5) & 7, kk = (idx >> 8) & 7, ph = idx >> 11;
        int k0 = kk * 8 + (lane & 3);
        int n  = nt * 8 + (lane >> 2);
        uint2 uu = make_uint2(f2tf(Wg[(ph * 64 + k0) * 64 + n]),
                              f2tf(Wg[(ph * 64 + k0 + 4) * 64 + n]));
        *(uint2*)(sW + idx * 2) = uu;
    }

    // --- stage broadcast features ---
    for (int idx = tid; idx < 1024; idx += 256) {
        int rr = idx >> 6, o = idx & 63;
        sFrI[idx] = g_Frow[(r0 + rr) * 64 + o];
        sFrJ[idx] = g_Frow[(c0 + rr) * 64 + o];
        sFcI[rr * 66 + o] = g_Fcol[(r0 + rr) * 64 + o];
        sFcJ[rr * 66 + o] = g_Fcol[(c0 + rr) * 64 + o];
        sG[idx] = g_G[(r0 + rr) * 64 + o];
    }

    // --- compute setup ---
    const int warp = tid >> 5, lane = tid & 31;
    const int oh   = warp >> 2;           // 0: output tile (I,J), 1: (J,I)
    const int wm   = warp & 3;
    const int rA = lane >> 2;
    const int cA = lane & 3;

    float acc[4][8][4];
#pragma unroll
    for (int m = 0; m < 4; m++)
#pragma unroll
        for (int n = 0; n < 8; n++)
#pragma unroll
            for (int j = 0; j < 4; j++) acc[m][n][j] = 0.f;

    // --- k-half pipelined mainloop ---
#pragma unroll
    for (int kh = 0; kh < 2; kh++) {
        if (kh == 0) asm volatile("cp.async.wait_group 1;");
        else         asm volatile("cp.async.wait_group 0;");
        __syncthreads();

        const uint32_t* bufN = (oh ? sB : sA) + kh * 8192;  // natural order (W0 phase)
        const uint32_t* bufT = (oh ? sA : sB) + kh * 8192;  // transposed order (W1 phase)

#pragma unroll
        for (int ph = 0; ph < 2; ph++) {
            const uint32_t* s = ph ? bufT : bufN;
#pragma unroll
            for (int kk = 0; kk < 4; kk++) {
                const int kk8 = kh * 4 + kk;       // absolute k-chunk 0..7
                const int kwa = kk * 8 + cA;       // k within half 0..31

                uint32_t a[4][4];
#pragma unroll
                for (int m = 0; m < 4; m++) {
                    int mt = wm * 4 + m;
#pragma unroll
                    for (int hh = 0; hh < 2; hh++) {
                        int e  = mt * 16 + rA + hh * 8;
                        int ee = ph ? (((e & 15) << 4) | (e >> 4)) : e;
                        int sw = ((ee ^ (ee >> 4)) & 7) << 2;
                        float f0 = __uint_as_float(s[ee * 32 + (kwa ^ sw)]);
                        float f1 = __uint_as_float(s[ee * 32 + ((kwa + 4) ^ sw)]);
                        a[m][hh]     = f2tf(f0);
                        a[m][hh + 2] = f2tf(f1);
                    }
                }

                uint32_t b[8][2];
#pragma unroll
                for (int nt = 0; nt < 8; nt++) {
                    uint2 w2 = *(const uint2*)(sW + (((ph * 8 + kk8) * 8 + nt) * 32 + lane) * 2);
                    b[nt][0] = w2.x; b[nt][1] = w2.y;
                }

#pragma unroll
                for (int m = 0; m < 4; m++)
#pragma unroll
                    for (int nt = 0; nt < 8; nt++)
                        mma_tf32(acc[m][nt], a[m], b[nt]);
            }
        }
    }

    // --- epilogue ---
    const int tI = oh ? J : I;
    const int tJ = oh ? I : J;
    const float* Fr = oh ? sFrJ : sFrI;
    const float* Fc = oh ? sFcI : sFcJ;
    const bool diagBlk = (I == J);
    const int c2 = (lane & 3) * 2;

#pragma unroll
    for (int nt = 0; nt < 8; nt++) {
        float2 fc0 = *(const float2*)(Fc + rA * 66 + nt * 8 + c2);
        float2 fc1 = *(const float2*)(Fc + (rA + 8) * 66 + nt * 8 + c2);
#pragma unroll
        for (int m = 0; m < 4; m++) {
            int mt = wm * 4 + m;
            float2 fr = *(const float2*)(Fr + mt * 64 + nt * 8 + c2);
            float v0 = acc[m][nt][0] + fr.x + fc0.x;
            float v1 = acc[m][nt][1] + fr.y + fc0.y;
            float v2 = acc[m][nt][2] + fr.x + fc1.x;
            float v3 = acc[m][nt][3] + fr.y + fc1.y;
            if (diagBlk) {
                if (mt == rA)     { v0 += sG[mt * 64 + nt * 8 + c2]; v1 += sG[mt * 64 + nt * 8 + c2 + 1]; }
                if (mt == rA + 8) { v2 += sG[mt * 64 + nt * 8 + c2]; v3 += sG[mt * 64 + nt * 8 + c2 + 1]; }
            }
            size_t base = ((size_t)(tI * 16 + mt) * N_DIM + tJ * 16 + rA) * 64 + nt * 8 + c2;
            *(float2*)(out + base)          = make_float2(v0, v1);
            *(float2*)(out + base + 8 * 64) = make_float2(v2, v3);
        }
    }
}

// ---------------- launch ----------------
extern "C" void kernel_launch(void* const* d_in, const int* in_sizes, int n_in,
                              void* d_out, int out_size) {
    const float* X = (const float*)d_in[0];   // [S, 64]
    const float* W = (const float*)d_in[1];   // [15, 64, 64]
    float* out = (float*)d_out;
    (void)in_sizes; (void)n_in; (void)out_size;

    rowpool_kernel<<<N_DIM, 256>>>(X);
    colpool_kernel<<<N_DIM, 256>>>(X);
    combine3_kernel<<<256, 256>>>(W);

    const int main_smem = (2 * 16384 + 8192 + 2 * 1024 + 2 * 1056 + 1024) * (int)sizeof(float); // ~180KB
    cudaFuncSetAttribute(main_mma_kernel, cudaFuncAttributeMaxDynamicSharedMemorySize, main_smem);
    main_mma_kernel<<<NPAIR, 256, main_smem>>>(X, W, out);
}